// round 12
// baseline (speedup 1.0000x reference)
#include <cuda_runtime.h>
#include <cuda_bf16.h>

// Contamination: out = 0.8*x + 0.2 * avg(valid neighbors at {-8,0,8}^2 \ {0,0})
// x: [B=8, C=32, H=512, W=512] fp32, k=8.
//
// R12 = R10 (96.6us; depth-2 center prefetch, 32-row tiles, 32 regs) with the
// CTA widened to span the FULL row: block (128,8)=1024 threads, grid.x=1.
// The side loads (c4 +/- 2) now always resolve inside the CTA, so the edge
// 128B lines are L1-resident (loaded by the adjacent warp on the SAME SM)
// instead of cross-SM L2 round-trips consumed same-iteration — the zero-
// register version of R11's fix (R11's register-cost version lost to the
// occupancy tax). Also removes all horizontal halo overfetch and shrinks the
// concurrent L2 footprint to ~28MB. lb(1024,2) -> 64 warps/SM at 32 regs.

namespace {

constexpr int H  = 512;
constexpr int W  = 512;
constexpr int K  = 8;
constexpr int W4 = W / 4;       // 128 float4 per row

__device__ __forceinline__ float4 f4zero() { return make_float4(0.f, 0.f, 0.f, 0.f); }

__device__ __forceinline__ float4 f4add(float4 a, float4 b) {
    return make_float4(a.x + b.x, a.y + b.y, a.z + b.z, a.w + b.w);
}

__global__ __launch_bounds__(1024, 2)
void contam_kernel(const float4* __restrict__ in, float4* __restrict__ out) {
    const int c4   = threadIdx.x;                     // float4 column, 0..127
    const int row0 = blockIdx.y * 32 + threadIdx.y;   // first output row (<=487)
    const int plane = blockIdx.z;

    const float4* __restrict__ pin  = in  + (size_t)plane * (H * W4);
    float4* __restrict__       pout = out + (size_t)plane * (H * W4);

    const bool hasL = (c4 >= 2);
    const bool hasR = (c4 <= W4 - 3);
    const int  nc   = 1 + (int)hasL + (int)hasR;

    // ---- prologue: Sprev (row0-K sum), Scur (row0 sum), cN = center(row0+K) ----
    float4 Sprev = f4zero();
    if (row0 >= K) {
        const float4* __restrict__ r = pin + (row0 - K) * W4;
        Sprev = r[c4];
        if (hasL) Sprev = f4add(Sprev, r[c4 - 2]);
        if (hasR) Sprev = f4add(Sprev, r[c4 + 2]);
    }
    float4 Scur;
    {
        const float4* __restrict__ r = pin + row0 * W4;
        Scur = r[c4];
        if (hasL) Scur = f4add(Scur, r[c4 - 2]);
        if (hasR) Scur = f4add(Scur, r[c4 + 2]);
    }
    float4 cN = pin[(row0 + K) * W4 + c4];   // row0+K <= 495, always valid

    #pragma unroll
    for (int ry = 0; ry < 4; ry++) {
        const int h   = row0 + ry * K;
        const int rn  = h + K;
        const bool vn = (rn < H);
        const int rn2 = h + 2 * K;
        const int rn2c = (rn2 < H) ? rn2 : h;   // clamped legal address

        // ---- batched issue: ctr (L1 hit), sides of row rn (L1-resident:
        //      center line prefetched last iter, edge lines loaded by the
        //      adjacent warp on this SM), prefetch center of h+2K (miss) ----
        const float4* __restrict__ rowC = pin + h * W4;
        const float4* __restrict__ rowN = pin + (vn ? rn : h) * W4;
        float4 ctr = rowC[c4];
        float4 s0  = hasL ? rowN[c4 - 2] : f4zero();
        float4 s2  = hasR ? rowN[c4 + 2] : f4zero();
        float4 cN2 = pin[rn2c * W4 + c4];

        float4 Snext = vn ? f4add(f4add(cN, s0), s2) : f4zero();

        const int nr = 1 + (int)(h >= K) + (int)vn;
        // count = nr*nc - 1 in {3,5,8}  <=>  nr+nc in {4,5,6}
        const int s  = nr + nc;
        const float scale = (s == 6) ? 0.025f
                          : (s == 5) ? 0.04f
                                     : 0.066666667f;

        float4 acc = f4add(f4add(Sprev, Scur), Snext);

        float4 o;
        o.x = 0.8f * ctr.x + scale * (acc.x - ctr.x);
        o.y = 0.8f * ctr.y + scale * (acc.y - ctr.y);
        o.z = 0.8f * ctr.z + scale * (acc.z - ctr.z);
        o.w = 0.8f * ctr.w + scale * (acc.w - ctr.w);

        __stcs(&pout[h * W4 + c4], o);

        Sprev = Scur;
        Scur  = Snext;
        cN    = cN2;
    }
}

} // namespace

extern "C" void kernel_launch(void* const* d_in, const int* in_sizes, int n_in,
                              void* d_out, int out_size) {
    const float4* x = (const float4*)d_in[0];
    float4* out = (float4*)d_out;

    const int planes = in_sizes[0] / (H * W);   // 256

    dim3 block(128, 8, 1);
    dim3 grid(1, H / 32, planes);               // (1, 16, 256)
    contam_kernel<<<grid, block>>>(x, out);
}